// round 10
// baseline (speedup 1.0000x reference)
#include <cuda_runtime.h>

#define NB 8
#define NP 4096
#define NG 96
#define BIGF 1e9f
#define PSLAB 64               // p-rows per build block
#define NSLAB (NP / PSLAB)     // 64 slabs
#define NT2 256                // lsa block size

// 12.6 MB scratch: transposed cost matrix, L2-resident.
__device__ float g_costT[NB][NG][NP];
// per-slab packed (fkey<<32 | p) minima: [batch][slab][g]
__device__ unsigned long long g_minpart[NB][NSLAB][NG];

// monotonic unsigned key for float ordering
__device__ __forceinline__ unsigned int fkey(float f) {
    unsigned int b = __float_as_uint(f);
    return b ^ ((b & 0x80000000u) ? 0xFFFFFFFFu : 0x80000000u);
}
__device__ __forceinline__ float funkey(unsigned int k) {
    return __uint_as_float(k ^ ((k & 0x80000000u) ? 0x80000000u : 0xFFFFFFFFu));
}

// ---------------------------------------------------------------------------
// Fused: cost = cd - 2*gi, transpose to costT[b][g][p], per-(g,slab) min.
// ---------------------------------------------------------------------------
__global__ void __launch_bounds__(256, 4)
build_cost_kernel(const float* __restrict__ cd, const float* __restrict__ gi) {
    __shared__ float tileT[NG][PSLAB + 1];

    const int b  = blockIdx.y;
    const int p0 = blockIdx.x * PSLAB;
    const int t  = threadIdx.x;

    const float4* cd4 = (const float4*)(cd + ((size_t)(b * NP + p0)) * NG);
    const float4* gi4 = (const float4*)(gi + ((size_t)(b * NP + p0)) * NG);
    #pragma unroll
    for (int it = 0; it < (PSLAB * (NG / 4)) / 256; ++it) {
        int i = t + it * 256;
        int p = i / (NG / 4);
        int k = i % (NG / 4);
        float4 a = cd4[i];
        float4 c = gi4[i];
        int g = 4 * k;
        tileT[g + 0][p] = a.x - 2.0f * c.x;
        tileT[g + 1][p] = a.y - 2.0f * c.y;
        tileT[g + 2][p] = a.z - 2.0f * c.z;
        tileT[g + 3][p] = a.w - 2.0f * c.w;
    }
    __syncthreads();

    #pragma unroll
    for (int it = 0; it < (NG * PSLAB) / 256; ++it) {
        int i = t + it * 256;
        int g = i / PSLAB;
        int p = i % PSLAB;
        g_costT[b][g][p0 + p] = tileT[g][p];
    }

    if (t < NG) {
        unsigned long long best = ~0ull;
        #pragma unroll 8
        for (int p = 0; p < PSLAB; ++p) {
            unsigned long long pk =
                ((unsigned long long)fkey(tileT[t][p]) << 32) | (unsigned int)(p0 + p);
            best = min(best, pk);
        }
        g_minpart[b][blockIdx.x][t] = best;   // plain store, no init needed
    }
}

// ---------------------------------------------------------------------------
// One CTA (256 threads) per batch. Thread t owns columns j = 4t + 1024k + m.
// shortest (sh), v (vv), SC (scmask), SR/rvals all register-resident.
// One __syncthreads per Dijkstra step; one per augmentation.
// ---------------------------------------------------------------------------
__global__ void __launch_bounds__(NT2, 1)
lsa_kernel(const int* __restrict__ nactual, float* __restrict__ out) {
    __shared__ int   path[NP];          // predecessor row per col (alias colwin)
    __shared__ int   row4col[NP];
    __shared__ float u[NG];
    __shared__ int   col4row[NG];
    __shared__ int   jmin_s[NG];
    __shared__ unsigned long long redp[2][8];

    const int b    = blockIdx.x;
    const int t    = threadIdx.x;
    const int lane = t & 31;
    const int w    = t >> 5;
    const int nact = nactual[b];

    float vv[16];
    #pragma unroll
    for (int q = 0; q < 16; ++q) vv[q] = 0.0f;

    // ---- per-batch init + greedy (JV row-reduction) assignment ----
    int* colwin = path;
    #pragma unroll
    for (int it = 0; it < NP / NT2; ++it) {
        int j = t + it * NT2;
        row4col[j] = -1;
        colwin[j] = 0x7fffffff;
    }
    if (t < NG) {
        unsigned long long best = ~0ull;
        #pragma unroll 8
        for (int s = 0; s < NSLAB; ++s)
            best = min(best, g_minpart[b][s][t]);   // coalesced across t
        u[t]       = funkey((unsigned int)(best >> 32));
        jmin_s[t]  = (int)(unsigned int)(best & 0xffffffffu);
        col4row[t] = -1;
    }
    __syncthreads();
    if (t < nact) atomicMin(&colwin[jmin_s[t]], t);
    __syncthreads();
    if (t < nact) {
        int j = jmin_s[t];
        if (colwin[j] == t) {            // lowest claimant wins
            col4row[t] = j;
            row4col[j] = t;
        }
    }
    __syncthreads();

    // ---- shortest augmenting path for each unassigned row ----
    for (int i = 0; i < nact; ++i) {
        if (col4row[i] >= 0) continue;

        float sh[16];
        #pragma unroll
        for (int q = 0; q < 16; ++q) sh[q] = BIGF;
        unsigned int scmask = 0;
        bool  lsr   = false;             // this thread's row (t<96) scanned?
        float lrval = 0.0f;              // value when it was scanned
        int   cur   = i;
        float minval = 0.0f;
        int   sink  = -1;
        int   par   = 0;

        while (true) {
            const float ucur = u[cur];
            const float4* __restrict__ crow4 = (const float4*)&g_costT[b][cur][0];
            float4 c0 = crow4[t];
            float4 c1 = crow4[t + 256];
            float4 c2 = crow4[t + 512];
            float4 c3 = crow4[t + 768];

            unsigned long long best = ~0ull;
            #define SCAN1(CF, K, M, BIT)                                        \
            {                                                                   \
                if (!((scmask >> (BIT)) & 1u)) {                                \
                    float red = ((minval + (CF)) - ucur) - vv[BIT];             \
                    int j = 4 * t + 1024 * (K) + (M);                           \
                    if (red < sh[BIT]) { sh[BIT] = red; path[j] = cur; }        \
                    unsigned long long pk =                                     \
                        ((unsigned long long)fkey(sh[BIT]) << 32) |             \
                        (unsigned int)j;                                        \
                    best = min(best, pk);                                       \
                }                                                               \
            }
            SCAN1(c0.x, 0, 0, 0)  SCAN1(c0.y, 0, 1, 1)
            SCAN1(c0.z, 0, 2, 2)  SCAN1(c0.w, 0, 3, 3)
            SCAN1(c1.x, 1, 0, 4)  SCAN1(c1.y, 1, 1, 5)
            SCAN1(c1.z, 1, 2, 6)  SCAN1(c1.w, 1, 3, 7)
            SCAN1(c2.x, 2, 0, 8)  SCAN1(c2.y, 2, 1, 9)
            SCAN1(c2.z, 2, 2, 10) SCAN1(c2.w, 2, 3, 11)
            SCAN1(c3.x, 3, 0, 12) SCAN1(c3.y, 3, 1, 13)
            SCAN1(c3.z, 3, 2, 14) SCAN1(c3.w, 3, 3, 15)
            #undef SCAN1

            // packed warp argmin (value, then lowest index)
            #pragma unroll
            for (int off = 16; off > 0; off >>= 1) {
                unsigned long long o = __shfl_down_sync(0xffffffffu, best, off);
                best = min(best, o);
            }
            if (lane == 0) redp[par][w] = best;
            __syncthreads();

            // redundant 8-way final reduce (all threads, no broadcast barrier)
            unsigned long long w0 = redp[par][0];
            #pragma unroll
            for (int q = 1; q < 8; ++q) w0 = min(w0, redp[par][q]);
            par ^= 1;

            const int j = (int)(unsigned int)(w0 & 0xffffffffu);
            minval = funkey((unsigned int)(w0 >> 32));
            if (((j & 1023) >> 2) == t)               // owner marks SC
                scmask |= 1u << (((j >> 10) << 2) | (j & 3));
            const int r = row4col[j];                 // smem broadcast
            if (r < 0) { sink = j; break; }
            if (t == r) { lsr = true; lrval = minval; }
            cur = r;
        }

        // ---- dual updates (registers) + augment (thread 0), concurrent ----
        if (t < NG) {
            if (t == i)     u[t] = u[t] + minval;
            else if (lsr)   u[t] = (u[t] + minval) - lrval;
        }
        #pragma unroll
        for (int q = 0; q < 16; ++q)
            if ((scmask >> q) & 1u) vv[q] = vv[q] - (minval - sh[q]);
        if (t == 0) {
            int j = sink;
            while (true) {
                int r = path[j];
                row4col[j] = r;
                int jn = col4row[r];
                col4row[r] = j;
                if (r == i) break;
                j = jn;
            }
        }
        __syncthreads();
    }

    // ---- epilogue ----
    float* out_inds = out;                 // [NB*NP] per_prop_gt_inds (as float)
    float* out_mask = out + NB * NP;       // [NB*NP] proposal_matched_mask
    float4 z4 = make_float4(0.f, 0.f, 0.f, 0.f);
    float4* oi4 = (float4*)(out_inds + b * NP);
    float4* om4 = (float4*)(out_mask + b * NP);
    #pragma unroll
    for (int it = 0; it < NP / 4 / NT2; ++it) {
        oi4[t + it * NT2] = z4;
        om4[t + it * NT2] = z4;
    }
    __syncthreads();
    if (t < nact) {
        int j = col4row[t];
        out_inds[b * NP + j] = (float)t;
        out_mask[b * NP + j] = 1.0f;
    }
}

// ---------------------------------------------------------------------------
extern "C" void kernel_launch(void* const* d_in, const int* in_sizes, int n_in,
                              void* d_out, int out_size) {
    const float* cd   = (const float*)d_in[0];   // center_dist [8,4096,96] f32
    const float* gi   = (const float*)d_in[1];   // gious       [8,4096,96] f32
    const int*   nact = (const int*)d_in[2];     // nactual_gt  [8] i32

    build_cost_kernel<<<dim3(NSLAB, NB), 256>>>(cd, gi);
    lsa_kernel<<<NB, NT2>>>(nact, (float*)d_out);
}

// round 13
// speedup vs baseline: 1.3726x; 1.3726x over previous
#include <cuda_runtime.h>

#define NB 8
#define NP 4096
#define NG 96
#define BIGF 1e9f
#define PSLAB 64               // p-rows per build block
#define NSLAB (NP / PSLAB)     // 64 slabs
#define NT2 256                // lsa block size

// 12.6 MB scratch: transposed cost matrix, L2-resident.
__device__ float g_costT[NB][NG][NP];
// per-slab packed (fkey<<32 | p) minima: [batch][slab][g]
__device__ unsigned long long g_minpart[NB][NSLAB][NG];

// monotonic unsigned key for float ordering
__device__ __forceinline__ unsigned int fkey(float f) {
    unsigned int b = __float_as_uint(f);
    return b ^ ((b & 0x80000000u) ? 0xFFFFFFFFu : 0x80000000u);
}
__device__ __forceinline__ float funkey(unsigned int k) {
    return __uint_as_float(k ^ ((k & 0x80000000u) ? 0x80000000u : 0xFFFFFFFFu));
}

// ---------------------------------------------------------------------------
// Fused: cost = cd - 2*gi, transpose to costT[b][g][p], per-(g,slab) min.
// Slab-0 blocks additionally zero the output (overlapped across the grid).
// ---------------------------------------------------------------------------
__global__ void __launch_bounds__(256, 4)
build_cost_kernel(const float* __restrict__ cd, const float* __restrict__ gi,
                  float* __restrict__ out) {
    __shared__ float tileT[NG][PSLAB + 1];

    const int b  = blockIdx.y;
    const int p0 = blockIdx.x * PSLAB;
    const int t  = threadIdx.x;

    const float4* cd4 = (const float4*)(cd + ((size_t)(b * NP + p0)) * NG);
    const float4* gi4 = (const float4*)(gi + ((size_t)(b * NP + p0)) * NG);
    #pragma unroll
    for (int it = 0; it < (PSLAB * (NG / 4)) / 256; ++it) {
        int i = t + it * 256;
        int p = i / (NG / 4);
        int k = i % (NG / 4);
        float4 a = cd4[i];
        float4 c = gi4[i];
        int g = 4 * k;
        tileT[g + 0][p] = a.x - 2.0f * c.x;
        tileT[g + 1][p] = a.y - 2.0f * c.y;
        tileT[g + 2][p] = a.z - 2.0f * c.z;
        tileT[g + 3][p] = a.w - 2.0f * c.w;
    }
    __syncthreads();

    #pragma unroll
    for (int it = 0; it < (NG * PSLAB) / 256; ++it) {
        int i = t + it * 256;
        int g = i / PSLAB;
        int p = i % PSLAB;
        g_costT[b][g][p0 + p] = tileT[g][p];
    }

    if (t < NG) {
        unsigned long long best = ~0ull;
        #pragma unroll 8
        for (int p = 0; p < PSLAB; ++p) {
            unsigned long long pk =
                ((unsigned long long)fkey(tileT[t][p]) << 32) | (unsigned int)(p0 + p);
            best = min(best, pk);
        }
        g_minpart[b][blockIdx.x][t] = best;   // plain store, no init needed
    }

    // zero this batch's output slice (inds + mask): 2*4096 floats = 2048 float4
    if (blockIdx.x == 0) {
        float4 z4 = make_float4(0.f, 0.f, 0.f, 0.f);
        float4* o4 = (float4*)(out + b * NP);
        float4* m4 = (float4*)(out + NB * NP + b * NP);
        #pragma unroll
        for (int it = 0; it < NP / 4 / 256; ++it) {
            o4[t + it * 256] = z4;
            m4[t + it * 256] = z4;
        }
    }
}

// ---------------------------------------------------------------------------
// One CTA (256 threads) per batch. Thread t owns columns j = 4t + 1024k + m.
// shortest (sh), v (vv), SC (scmask), SR/rvals register-resident.
// One __syncthreads per Dijkstra step; one per augmentation.
// ---------------------------------------------------------------------------
__global__ void __launch_bounds__(NT2, 1)
lsa_kernel(const int* __restrict__ nactual, float* __restrict__ out) {
    __shared__ int   path[NP];          // predecessor row per col (alias colwin)
    __shared__ int   row4col[NP];
    __shared__ float u[NG];
    __shared__ int   col4row[NG];
    __shared__ int   jmin_s[NG];
    __shared__ int   conf[NG];          // conflicted rows after greedy
    __shared__ int   s_nconf;
    __shared__ unsigned long long redp[2][8];

    const int b    = blockIdx.x;
    const int t    = threadIdx.x;
    const int lane = t & 31;
    const int w    = t >> 5;
    const int nact = nactual[b];

    float vv[16];
    #pragma unroll
    for (int q = 0; q < 16; ++q) vv[q] = 0.0f;

    // ---- per-batch init ----
    int* colwin = path;
    #pragma unroll
    for (int it = 0; it < NP / NT2; ++it) {
        int j = t + it * NT2;
        row4col[j] = -1;
        colwin[j] = 0x7fffffff;
    }
    if (t == 0) s_nconf = 0;
    // parallel 64-slab min reduce: threads 2g, 2g+1 split slabs, shfl combine
    if (t < 2 * NG) {
        const int g = t >> 1, h = t & 1;
        unsigned long long best = ~0ull;
        #pragma unroll 8
        for (int s = 32 * h; s < 32 * h + 32; ++s)
            best = min(best, g_minpart[b][s][g]);
        unsigned long long o = __shfl_xor_sync(0xffffffffu, best, 1);
        best = min(best, o);
        if (h == 0) {
            u[g]       = funkey((unsigned int)(best >> 32));
            jmin_s[g]  = (int)(unsigned int)(best & 0xffffffffu);
            col4row[g] = -1;
        }
    }
    __syncthreads();

    // ---- greedy (JV row-reduction) assignment ----
    if (t < nact) atomicMin(&colwin[jmin_s[t]], t);
    __syncthreads();
    if (t < nact) {
        int j = jmin_s[t];
        if (colwin[j] == t) {            // lowest claimant wins
            col4row[t] = j;
            row4col[j] = t;
        } else {
            int s = atomicAdd(&s_nconf, 1);
            conf[s] = t;                 // conflict list
        }
    }
    __syncthreads();
    const int nconf = s_nconf;

    // ---- shortest augmenting path for each conflicted row ----
    for (int ci = 0; ci < nconf; ++ci) {
        const int i = conf[ci];

        float sh[16];
        #pragma unroll
        for (int q = 0; q < 16; ++q) sh[q] = BIGF;
        unsigned int scmask = 0;
        bool  lsr    = false;            // this thread's row (t<96) scanned?
        float lrval  = 0.0f;             // value when it was scanned
        int   cur    = i;
        float minval = 0.0f;
        int   sink   = -1;
        int   par    = 0;

        while (true) {
            const float ucur = u[cur];
            const float4* __restrict__ crow4 = (const float4*)&g_costT[b][cur][0];
            float4 c0 = crow4[t];
            float4 c1 = crow4[t + 256];
            float4 c2 = crow4[t + 512];
            float4 c3 = crow4[t + 768];

            // 4 independent (val,idx) chains, then 2-level merge (exact ties)
            float lv0 = BIGF, lv1 = BIGF, lv2 = BIGF, lv3 = BIGF;
            int   li0 = NP,   li1 = NP,   li2 = NP,   li3 = NP;
            #define ELT(C, K, M, BIT, LV, LI)                                   \
            {                                                                   \
                const unsigned int scb = (scmask >> (BIT)) & 1u;                \
                float red = ((minval + (C)) - ucur) - vv[BIT];                  \
                if (!scb && red < sh[BIT]) {                                    \
                    sh[BIT] = red;                                              \
                    path[4 * t + 1024 * (K) + (M)] = cur;                       \
                }                                                               \
                float cand = scb ? BIGF : sh[BIT];                              \
                if (cand < LV) { LV = cand; LI = 4 * t + 1024 * (K) + (M); }    \
            }
            ELT(c0.x, 0, 0, 0,  lv0, li0) ELT(c0.y, 0, 1, 1,  lv0, li0)
            ELT(c0.z, 0, 2, 2,  lv0, li0) ELT(c0.w, 0, 3, 3,  lv0, li0)
            ELT(c1.x, 1, 0, 4,  lv1, li1) ELT(c1.y, 1, 1, 5,  lv1, li1)
            ELT(c1.z, 1, 2, 6,  lv1, li1) ELT(c1.w, 1, 3, 7,  lv1, li1)
            ELT(c2.x, 2, 0, 8,  lv2, li2) ELT(c2.y, 2, 1, 9,  lv2, li2)
            ELT(c2.z, 2, 2, 10, lv2, li2) ELT(c2.w, 2, 3, 11, lv2, li2)
            ELT(c3.x, 3, 0, 12, lv3, li3) ELT(c3.y, 3, 1, 13, lv3, li3)
            ELT(c3.z, 3, 2, 14, lv3, li3) ELT(c3.w, 3, 3, 15, lv3, li3)
            #undef ELT
            // merge: lower-k group wins ties (lower j)
            if (lv1 < lv0) { lv0 = lv1; li0 = li1; }
            if (lv3 < lv2) { lv2 = lv3; li2 = li3; }
            if (lv2 < lv0) { lv0 = lv2; li0 = li2; }

            // pack once, u64 shuffle-min (value, then lowest index)
            unsigned long long best =
                ((unsigned long long)fkey(lv0) << 32) | (unsigned int)li0;
            #pragma unroll
            for (int off = 16; off > 0; off >>= 1) {
                unsigned long long o = __shfl_down_sync(0xffffffffu, best, off);
                best = min(best, o);
            }
            if (lane == 0) redp[par][w] = best;
            __syncthreads();

            // redundant 8-slot tree reduce (all threads, no broadcast barrier)
            unsigned long long a0 = min(redp[par][0], redp[par][1]);
            unsigned long long a1 = min(redp[par][2], redp[par][3]);
            unsigned long long a2 = min(redp[par][4], redp[par][5]);
            unsigned long long a3 = min(redp[par][6], redp[par][7]);
            unsigned long long w0 = min(min(a0, a1), min(a2, a3));
            par ^= 1;

            const int j = (int)(unsigned int)(w0 & 0xffffffffu);
            minval = funkey((unsigned int)(w0 >> 32));
            const int r = row4col[j];                 // smem broadcast
            if (((j & 1023) >> 2) == t)               // owner marks SC
                scmask |= 1u << (((j >> 10) << 2) | (j & 3));
            if (r < 0) { sink = j; break; }
            if (t == r) { lsr = true; lrval = minval; }
            cur = r;
        }

        // ---- dual updates (registers) + augment (thread 0), concurrent ----
        if (t < NG) {
            if (t == i)     u[t] = u[t] + minval;
            else if (lsr)   u[t] = (u[t] + minval) - lrval;
        }
        #pragma unroll
        for (int q = 0; q < 16; ++q)
            if ((scmask >> q) & 1u) vv[q] = vv[q] - (minval - sh[q]);
        if (t == 0) {
            int j = sink;
            while (true) {
                int r = path[j];
                row4col[j] = r;
                int jn = col4row[r];
                col4row[r] = j;
                if (r == i) break;
                j = jn;
            }
        }
        __syncthreads();
    }

    // ---- epilogue: scatter only (zeroing done by build kernel) ----
    if (t < nact) {
        int j = col4row[t];
        out[b * NP + j] = (float)t;               // per_prop_gt_inds
        out[NB * NP + b * NP + j] = 1.0f;         // proposal_matched_mask
    }
}

// ---------------------------------------------------------------------------
extern "C" void kernel_launch(void* const* d_in, const int* in_sizes, int n_in,
                              void* d_out, int out_size) {
    const float* cd   = (const float*)d_in[0];   // center_dist [8,4096,96] f32
    const float* gi   = (const float*)d_in[1];   // gious       [8,4096,96] f32
    const int*   nact = (const int*)d_in[2];     // nactual_gt  [8] i32

    build_cost_kernel<<<dim3(NSLAB, NB), 256>>>(cd, gi, (float*)d_out);
    lsa_kernel<<<NB, NT2>>>(nact, (float*)d_out);
}

// round 16
// speedup vs baseline: 1.4220x; 1.0360x over previous
#include <cuda_runtime.h>

#define NB 8
#define NP 4096
#define NG 96
#define BIGF 1e9f
#define PSLAB 64               // p-rows per build block
#define NSLAB (NP / PSLAB)     // 64 slabs
#define NT2 256                // lsa block size

// 12.6 MB scratch: transposed cost matrix, L2-resident.
__device__ float g_costT[NB][NG][NP];
// per-slab packed (fkey<<32 | p) minima: [batch][slab][g]
__device__ unsigned long long g_minpart[NB][NSLAB][NG];

// monotonic unsigned key for float ordering
__device__ __forceinline__ unsigned int fkey(float f) {
    unsigned int b = __float_as_uint(f);
    return b ^ ((b & 0x80000000u) ? 0xFFFFFFFFu : 0x80000000u);
}
__device__ __forceinline__ float funkey(unsigned int k) {
    return __uint_as_float(k ^ ((k & 0x80000000u) ? 0x80000000u : 0xFFFFFFFFu));
}

// ---------------------------------------------------------------------------
// Fused: cost = cd - 2*gi, transpose to costT[b][g][p], per-(g,slab) min.
// Slab-0 blocks additionally zero the output (overlapped across the grid).
// ---------------------------------------------------------------------------
__global__ void __launch_bounds__(256, 4)
build_cost_kernel(const float* __restrict__ cd, const float* __restrict__ gi,
                  float* __restrict__ out) {
    __shared__ float tileT[NG][PSLAB + 1];

    const int b  = blockIdx.y;
    const int p0 = blockIdx.x * PSLAB;
    const int t  = threadIdx.x;

    const float4* cd4 = (const float4*)(cd + ((size_t)(b * NP + p0)) * NG);
    const float4* gi4 = (const float4*)(gi + ((size_t)(b * NP + p0)) * NG);
    #pragma unroll
    for (int it = 0; it < (PSLAB * (NG / 4)) / 256; ++it) {
        int i = t + it * 256;
        int p = i / (NG / 4);
        int k = i % (NG / 4);
        float4 a = cd4[i];
        float4 c = gi4[i];
        int g = 4 * k;
        tileT[g + 0][p] = a.x - 2.0f * c.x;
        tileT[g + 1][p] = a.y - 2.0f * c.y;
        tileT[g + 2][p] = a.z - 2.0f * c.z;
        tileT[g + 3][p] = a.w - 2.0f * c.w;
    }
    __syncthreads();

    #pragma unroll
    for (int it = 0; it < (NG * PSLAB) / 256; ++it) {
        int i = t + it * 256;
        int g = i / PSLAB;
        int p = i % PSLAB;
        g_costT[b][g][p0 + p] = tileT[g][p];
    }

    if (t < NG) {
        unsigned long long best = ~0ull;
        #pragma unroll 8
        for (int p = 0; p < PSLAB; ++p) {
            unsigned long long pk =
                ((unsigned long long)fkey(tileT[t][p]) << 32) | (unsigned int)(p0 + p);
            best = min(best, pk);
        }
        g_minpart[b][blockIdx.x][t] = best;   // plain store, no init needed
    }

    // zero this batch's output slice (inds + mask): 2*4096 floats = 2048 float4
    if (blockIdx.x == 0) {
        float4 z4 = make_float4(0.f, 0.f, 0.f, 0.f);
        float4* o4 = (float4*)(out + b * NP);
        float4* m4 = (float4*)(out + NB * NP + b * NP);
        #pragma unroll
        for (int it = 0; it < NP / 4 / 256; ++it) {
            o4[t + it * 256] = z4;
            m4[t + it * 256] = z4;
        }
    }
}

// ---------------------------------------------------------------------------
// One CTA (256 threads) per batch. Thread t owns columns j = 4t + 1024k + m.
// shortest (sh), v (vv), SC (scmask), SR/rvals register-resident.
// One __syncthreads per Dijkstra step; one per augmentation.
// ---------------------------------------------------------------------------
__global__ void __launch_bounds__(NT2, 1)
lsa_kernel(const int* __restrict__ nactual, float* __restrict__ out) {
    __shared__ int   path[NP];          // predecessor row per col (alias colwin)
    __shared__ int   row4col[NP];
    __shared__ float u[NG];
    __shared__ int   col4row[NG];
    __shared__ int   jmin_s[NG];
    __shared__ int   conf[NG];          // conflicted rows after greedy
    __shared__ int   s_nconf;
    __shared__ unsigned long long redp[2][8];

    const int b    = blockIdx.x;
    const int t    = threadIdx.x;
    const int lane = t & 31;
    const int w    = t >> 5;
    const int nact = nactual[b];

    float vv[16];
    #pragma unroll
    for (int q = 0; q < 16; ++q) vv[q] = 0.0f;

    // ---- per-batch init ----
    int* colwin = path;
    #pragma unroll
    for (int it = 0; it < NP / NT2; ++it) {
        int j = t + it * NT2;
        row4col[j] = -1;
        colwin[j] = 0x7fffffff;
    }
    if (t == 0) s_nconf = 0;
    // parallel 64-slab min reduce: threads 2g, 2g+1 split slabs, shfl combine
    if (t < 2 * NG) {
        const int g = t >> 1, h = t & 1;
        unsigned long long best = ~0ull;
        #pragma unroll 8
        for (int s = 32 * h; s < 32 * h + 32; ++s)
            best = min(best, g_minpart[b][s][g]);
        unsigned long long o = __shfl_xor_sync(0xffffffffu, best, 1);
        best = min(best, o);
        if (h == 0) {
            u[g]       = funkey((unsigned int)(best >> 32));
            jmin_s[g]  = (int)(unsigned int)(best & 0xffffffffu);
            col4row[g] = -1;
        }
    }
    __syncthreads();

    // ---- greedy (JV row-reduction) assignment ----
    if (t < nact) atomicMin(&colwin[jmin_s[t]], t);
    __syncthreads();
    if (t < nact) {
        int j = jmin_s[t];
        if (colwin[j] == t) {            // lowest claimant wins
            col4row[t] = j;
            row4col[j] = t;
        } else {
            int s = atomicAdd(&s_nconf, 1);
            conf[s] = t;                 // conflict list
        }
    }
    __syncthreads();
    const int nconf = s_nconf;
    bool first_sap = true;

    // ---- shortest augmenting path for each conflicted row ----
    for (int ci = 0; ci < nconf; ++ci) {
        const int i = conf[ci];

        float sh[16];
        #pragma unroll
        for (int q = 0; q < 16; ++q) sh[q] = BIGF;
        unsigned int scmask = 0;
        bool  lsr    = false;            // this thread's row (t<96) scanned?
        float lrval  = 0.0f;             // value when it was scanned
        int   cur    = i;
        float minval = 0.0f;
        int   sink   = -1;
        int   par    = 0;
        bool  seeded = false;

        if (first_sap) {
            // Seeded step 1: with v==0 and u=rowmins, the argmin over
            // red[j] = c[i][j]-u[i] is provably jmin_s[i] with minval = 0.0f
            // (c[i][jmin]-u[i] == 0 exactly). Populate sh/path via the scan,
            // but skip the reduce + barrier entirely.
            const float ucur = u[i];
            const float4* __restrict__ crow4 = (const float4*)&g_costT[b][i][0];
            float4 c0 = crow4[t];
            float4 c1 = crow4[t + 256];
            float4 c2 = crow4[t + 512];
            float4 c3 = crow4[t + 768];
            #define SEED1(C, K, M, BIT)                                         \
            {                                                                   \
                float red = ((0.0f + (C)) - ucur) - vv[BIT];                    \
                if (red < sh[BIT]) {                                            \
                    sh[BIT] = red;                                              \
                    path[4 * t + 1024 * (K) + (M)] = i;                         \
                }                                                               \
            }
            SEED1(c0.x, 0, 0, 0)  SEED1(c0.y, 0, 1, 1)
            SEED1(c0.z, 0, 2, 2)  SEED1(c0.w, 0, 3, 3)
            SEED1(c1.x, 1, 0, 4)  SEED1(c1.y, 1, 1, 5)
            SEED1(c1.z, 1, 2, 6)  SEED1(c1.w, 1, 3, 7)
            SEED1(c2.x, 2, 0, 8)  SEED1(c2.y, 2, 1, 9)
            SEED1(c2.z, 2, 2, 10) SEED1(c2.w, 2, 3, 11)
            SEED1(c3.x, 3, 0, 12) SEED1(c3.y, 3, 1, 13)
            SEED1(c3.z, 3, 2, 14) SEED1(c3.w, 3, 3, 15)
            #undef SEED1
            const int j = jmin_s[i];
            minval = 0.0f;
            if (((j & 1023) >> 2) == t)               // owner marks SC
                scmask |= 1u << (((j >> 10) << 2) | (j & 3));
            const int r = row4col[j];                 // assigned (it conflicted)
            if (t == r) { lsr = true; lrval = 0.0f; }
            cur = r;
            seeded = true;
        }

        while (true) {
            const float ucur = u[cur];
            const float4* __restrict__ crow4 = (const float4*)&g_costT[b][cur][0];
            float4 c0 = crow4[t];
            float4 c1 = crow4[t + 256];
            float4 c2 = crow4[t + 512];
            float4 c3 = crow4[t + 768];

            // 4 independent (val,idx) chains, then 2-level merge (exact ties)
            float lv0 = BIGF, lv1 = BIGF, lv2 = BIGF, lv3 = BIGF;
            int   li0 = NP,   li1 = NP,   li2 = NP,   li3 = NP;
            #define ELT(C, K, M, BIT, LV, LI)                                   \
            {                                                                   \
                const unsigned int scb = (scmask >> (BIT)) & 1u;                \
                float red = ((minval + (C)) - ucur) - vv[BIT];                  \
                if (!scb && red < sh[BIT]) {                                    \
                    sh[BIT] = red;                                              \
                    path[4 * t + 1024 * (K) + (M)] = cur;                       \
                }                                                               \
                float cand = scb ? BIGF : sh[BIT];                              \
                if (cand < LV) { LV = cand; LI = 4 * t + 1024 * (K) + (M); }    \
            }
            ELT(c0.x, 0, 0, 0,  lv0, li0) ELT(c0.y, 0, 1, 1,  lv0, li0)
            ELT(c0.z, 0, 2, 2,  lv0, li0) ELT(c0.w, 0, 3, 3,  lv0, li0)
            ELT(c1.x, 1, 0, 4,  lv1, li1) ELT(c1.y, 1, 1, 5,  lv1, li1)
            ELT(c1.z, 1, 2, 6,  lv1, li1) ELT(c1.w, 1, 3, 7,  lv1, li1)
            ELT(c2.x, 2, 0, 8,  lv2, li2) ELT(c2.y, 2, 1, 9,  lv2, li2)
            ELT(c2.z, 2, 2, 10, lv2, li2) ELT(c2.w, 2, 3, 11, lv2, li2)
            ELT(c3.x, 3, 0, 12, lv3, li3) ELT(c3.y, 3, 1, 13, lv3, li3)
            ELT(c3.z, 3, 2, 14, lv3, li3) ELT(c3.w, 3, 3, 15, lv3, li3)
            #undef ELT
            // merge: lower-k group wins ties (lower j)
            if (lv1 < lv0) { lv0 = lv1; li0 = li1; }
            if (lv3 < lv2) { lv2 = lv3; li2 = li3; }
            if (lv2 < lv0) { lv0 = lv2; li0 = li2; }

            // warp argmin via two REDUX ops: min value, then lowest index
            unsigned int key  = fkey(lv0);
            unsigned int vmin = __reduce_min_sync(0xffffffffu, key);
            unsigned int cidx = (key == vmin) ? (unsigned int)li0 : 0xffffffffu;
            unsigned int imin = __reduce_min_sync(0xffffffffu, cidx);
            if (lane == 0)
                redp[par][w] = ((unsigned long long)vmin << 32) | imin;
            __syncthreads();

            // redundant 8-slot tree reduce (all threads, no broadcast barrier)
            unsigned long long a0 = min(redp[par][0], redp[par][1]);
            unsigned long long a1 = min(redp[par][2], redp[par][3]);
            unsigned long long a2 = min(redp[par][4], redp[par][5]);
            unsigned long long a3 = min(redp[par][6], redp[par][7]);
            unsigned long long w0 = min(min(a0, a1), min(a2, a3));
            par ^= 1;

            const int j = (int)(unsigned int)(w0 & 0xffffffffu);
            minval = funkey((unsigned int)(w0 >> 32));
            const int r = row4col[j];                 // smem broadcast
            if (((j & 1023) >> 2) == t)               // owner marks SC
                scmask |= 1u << (((j >> 10) << 2) | (j & 3));
            if (r < 0) { sink = j; break; }
            if (t == r) { lsr = true; lrval = minval; }
            cur = r;
        }
        (void)seeded;
        first_sap = false;

        // ---- dual updates (registers) + augment (thread 0), concurrent ----
        if (t < NG) {
            if (t == i)     u[t] = u[t] + minval;
            else if (lsr)   u[t] = (u[t] + minval) - lrval;
        }
        #pragma unroll
        for (int q = 0; q < 16; ++q)
            if ((scmask >> q) & 1u) vv[q] = vv[q] - (minval - sh[q]);
        if (t == 0) {
            int j = sink;
            while (true) {
                int r = path[j];
                row4col[j] = r;
                int jn = col4row[r];
                col4row[r] = j;
                if (r == i) break;
                j = jn;
            }
        }
        __syncthreads();
    }

    // ---- epilogue: scatter only (zeroing done by build kernel) ----
    if (t < nact) {
        int j = col4row[t];
        out[b * NP + j] = (float)t;               // per_prop_gt_inds
        out[NB * NP + b * NP + j] = 1.0f;         // proposal_matched_mask
    }
}

// ---------------------------------------------------------------------------
extern "C" void kernel_launch(void* const* d_in, const int* in_sizes, int n_in,
                              void* d_out, int out_size) {
    const float* cd   = (const float*)d_in[0];   // center_dist [8,4096,96] f32
    const float* gi   = (const float*)d_in[1];   // gious       [8,4096,96] f32
    const int*   nact = (const int*)d_in[2];     // nactual_gt  [8] i32

    build_cost_kernel<<<dim3(NSLAB, NB), 256>>>(cd, gi, (float*)d_out);
    lsa_kernel<<<NB, NT2>>>(nact, (float*)d_out);
}